// round 2
// baseline (speedup 1.0000x reference)
#include <cuda_runtime.h>
#include <cuda_bf16.h>
#include <cstdint>

// ---------------- problem constants ----------------
#define D_     256
#define NH_    8
#define DH_    32
#define NS_    12
#define NP_    4
#define HB_    200
#define WB_    200
#define V_     (HB_*WB_)       // 40000
#define BS_    2
#define A_     256
#define M_     6
#define NQ_    (A_*M_)         // 1536
#define ROWS_  (BS_*NQ_)       // 3072
#define LN_EPS 1e-5f

// ---------------- device scratch (static, allocation-free) ----------------
__device__ __align__(16) float g_vimg[(size_t)BS_*NH_*V_*DH_];     // [b][h][pix][dh]
__device__ __align__(16) float g_off [(size_t)ROWS_*768];          // offset GEMM out
__device__ __align__(16) float g_aw  [(size_t)ROWS_*384];          // attn logits GEMM out
__device__ __align__(16) float4 g_scw[(size_t)ROWS_*NS_*NH_*NP_];  // (x, y, weight, pad)
__device__ __align__(16) float g_samp[(size_t)ROWS_*NS_*D_];       // sampled, (3072, 3072)
__device__ __align__(16) float g_o   [(size_t)ROWS_*D_];           // pre-LN projection out

// ---------------- query projections: C = (query+query_pos) @ W + b ----------------
// dst_sel: 0 -> g_off (N=768), 1 -> g_aw (N=384). M=3072, K=256.
__global__ __launch_bounds__(256) void gemm_qproj(
    const float* __restrict__ Aq, const float* __restrict__ Ap,
    const float* __restrict__ B, const float* __restrict__ bias, int N, int dst_sel)
{
    __shared__ float As[16][64];
    __shared__ float Bs[16][64];
    float* __restrict__ C = dst_sel ? g_aw : g_off;
    const int tid = threadIdx.x;
    const int tx = tid & 15, ty = tid >> 4;
    const int row0 = blockIdx.y * 64;
    const int col0 = blockIdx.x * 64;
    const int a_m = tid >> 2, a_k = (tid & 3) << 2;
    const int b_k = tid >> 4, b_n = (tid & 15) << 2;

    float acc[4][4] = {};
    for (int k0 = 0; k0 < 256; k0 += 16) {
        float4 av = *reinterpret_cast<const float4*>(&Aq[(size_t)(row0 + a_m) * 256 + k0 + a_k]);
        float4 pv = *reinterpret_cast<const float4*>(&Ap[(size_t)(row0 + a_m) * 256 + k0 + a_k]);
        av.x += pv.x; av.y += pv.y; av.z += pv.z; av.w += pv.w;
        As[a_k + 0][a_m] = av.x;
        As[a_k + 1][a_m] = av.y;
        As[a_k + 2][a_m] = av.z;
        As[a_k + 3][a_m] = av.w;
        *reinterpret_cast<float4*>(&Bs[b_k][b_n]) =
            *reinterpret_cast<const float4*>(&B[(size_t)(k0 + b_k) * N + col0 + b_n]);
        __syncthreads();
        #pragma unroll
        for (int k = 0; k < 16; k++) {
            float am[4], bn[4];
            #pragma unroll
            for (int i = 0; i < 4; i++) am[i] = As[k][ty * 4 + i];
            #pragma unroll
            for (int j = 0; j < 4; j++) bn[j] = Bs[k][tx * 4 + j];
            #pragma unroll
            for (int i = 0; i < 4; i++)
                #pragma unroll
                for (int j = 0; j < 4; j++) acc[i][j] += am[i] * bn[j];
        }
        __syncthreads();
    }
    const int col = col0 + tx * 4;
    float4 bv = *reinterpret_cast<const float4*>(&bias[col]);
    #pragma unroll
    for (int i = 0; i < 4; i++) {
        int row = row0 + ty * 4 + i;
        float4 o = make_float4(acc[i][0] + bv.x, acc[i][1] + bv.y,
                               acc[i][2] + bv.z, acc[i][3] + bv.w);
        *reinterpret_cast<float4*>(&C[(size_t)row * N + col]) = o;
    }
}

// ---------------- output projection: g_o = g_samp @ W_out + b_out ----------------
// M=3072, N=256, K=3072.
__global__ __launch_bounds__(256) void gemm_out(
    const float* __restrict__ B, const float* __restrict__ bias)
{
    __shared__ float As[16][64];
    __shared__ float Bs[16][64];
    const int tid = threadIdx.x;
    const int tx = tid & 15, ty = tid >> 4;
    const int row0 = blockIdx.y * 64;
    const int col0 = blockIdx.x * 64;
    const int a_m = tid >> 2, a_k = (tid & 3) << 2;
    const int b_k = tid >> 4, b_n = (tid & 15) << 2;

    float acc[4][4] = {};
    for (int k0 = 0; k0 < 3072; k0 += 16) {
        float4 av = *reinterpret_cast<const float4*>(&g_samp[(size_t)(row0 + a_m) * 3072 + k0 + a_k]);
        As[a_k + 0][a_m] = av.x;
        As[a_k + 1][a_m] = av.y;
        As[a_k + 2][a_m] = av.z;
        As[a_k + 3][a_m] = av.w;
        *reinterpret_cast<float4*>(&Bs[b_k][b_n]) =
            *reinterpret_cast<const float4*>(&B[(size_t)(k0 + b_k) * 256 + col0 + b_n]);
        __syncthreads();
        #pragma unroll
        for (int k = 0; k < 16; k++) {
            float am[4], bn[4];
            #pragma unroll
            for (int i = 0; i < 4; i++) am[i] = As[k][ty * 4 + i];
            #pragma unroll
            for (int j = 0; j < 4; j++) bn[j] = Bs[k][tx * 4 + j];
            #pragma unroll
            for (int i = 0; i < 4; i++)
                #pragma unroll
                for (int j = 0; j < 4; j++) acc[i][j] += am[i] * bn[j];
        }
        __syncthreads();
    }
    const int col = col0 + tx * 4;
    float4 bv = *reinterpret_cast<const float4*>(&bias[col]);
    #pragma unroll
    for (int i = 0; i < 4; i++) {
        int row = row0 + ty * 4 + i;
        float4 o = make_float4(acc[i][0] + bv.x, acc[i][1] + bv.y,
                               acc[i][2] + bv.z, acc[i][3] + bv.w);
        *reinterpret_cast<float4*>(&g_o[(size_t)row * 256 + col]) = o;
    }
}

// ---------------- value projection GEMM with fused layout scatter ----------------
// Input: value (V, BS, D). Logical row r = b*V + pix is value[pix][b][:].
// Output scattered directly to g_vimg[b][h][pix][dh] (128B-coalescible lines).
// M = 80000; 64-row blocks never straddle b (40000 % 64 == 0).
__global__ __launch_bounds__(256) void gemm_val(
    const float* __restrict__ value, const float* __restrict__ W,
    const float* __restrict__ bias)
{
    __shared__ float As[16][64];
    __shared__ float Bs[16][64];
    const int tid = threadIdx.x;
    const int tx = tid & 15, ty = tid >> 4;
    const int row0 = blockIdx.y * 64;
    const int col0 = blockIdx.x * 64;
    const int bb = (row0 >= V_) ? 1 : 0;
    const int pix0 = row0 - bb * V_;
    const int a_m = tid >> 2, a_k = (tid & 3) << 2;
    const int b_k = tid >> 4, b_n = (tid & 15) << 2;
    const float* Arow = value + ((size_t)(pix0 + a_m) * BS_ + bb) * D_;

    float acc[4][4] = {};
    for (int k0 = 0; k0 < 256; k0 += 16) {
        float4 av = *reinterpret_cast<const float4*>(Arow + k0 + a_k);
        As[a_k + 0][a_m] = av.x;
        As[a_k + 1][a_m] = av.y;
        As[a_k + 2][a_m] = av.z;
        As[a_k + 3][a_m] = av.w;
        *reinterpret_cast<float4*>(&Bs[b_k][b_n]) =
            *reinterpret_cast<const float4*>(&W[(size_t)(k0 + b_k) * 256 + col0 + b_n]);
        __syncthreads();
        #pragma unroll
        for (int k = 0; k < 16; k++) {
            float am[4], bn[4];
            #pragma unroll
            for (int i = 0; i < 4; i++) am[i] = As[k][ty * 4 + i];
            #pragma unroll
            for (int j = 0; j < 4; j++) bn[j] = Bs[k][tx * 4 + j];
            #pragma unroll
            for (int i = 0; i < 4; i++)
                #pragma unroll
                for (int j = 0; j < 4; j++) acc[i][j] += am[i] * bn[j];
        }
        __syncthreads();
    }
    const int col = col0 + tx * 4;           // 4 consecutive channels, same head
    const int h = col >> 5, dh = col & 31;
    float4 bv = *reinterpret_cast<const float4*>(&bias[col]);
    #pragma unroll
    for (int i = 0; i < 4; i++) {
        int pix = pix0 + ty * 4 + i;
        float4 o = make_float4(acc[i][0] + bv.x, acc[i][1] + bv.y,
                               acc[i][2] + bv.z, acc[i][3] + bv.w);
        *reinterpret_cast<float4*>(
            &g_vimg[(((size_t)(bb * NH_ + h)) * V_ + pix) * DH_ + dh]) = o;
    }
}

// ---------------- softmax + sampling-coordinate precompute ----------------
// One thread per (row r, head h, step s): softmax over NP=4 logits, pixel-space
// x/y per point (x = (locx*2-1 +1)*W/2 - 0.5 = locx*W - 0.5), store (x,y,w).
__global__ __launch_bounds__(256) void coords_softmax(
    const float* __restrict__ trajs, const float* __restrict__ centers)
{
    int gid = blockIdx.x * blockDim.x + threadIdx.x;
    if (gid >= ROWS_ * NH_ * NS_) return;
    int r = gid / (NH_ * NS_);
    int rem = gid - r * (NH_ * NS_);
    int h = rem / NS_;
    int s = rem - h * NS_;
    int b = r / NQ_;
    int q = r - b * NQ_;
    int a = q / M_;
    // reference point: trajs[b][a][m][NS-1][0][:] + det_centers[b][a][:]
    const float* tr = trajs + ((size_t)(((b * A_ + a) * M_ + (q - a * M_)) * NS_ + (NS_ - 1))) * 2;
    float cx = centers[(b * A_ + a) * 2 + 0];
    float cy = centers[(b * A_ + a) * 2 + 1];
    const float sc = 200.0f / 102.4f;   // W / (bev extent); normalized*W - 0.5
    float xb = (tr[0] + cx + 51.2f) * sc - 0.5f;
    float yb = (tr[1] + cy + 51.2f) * sc - 0.5f;

    const float* awp  = g_aw  + (size_t)r * 384 + h * (NS_ * NP_) + s * NP_;
    const float* offp = g_off + (size_t)r * 768 + h * (NS_ * NP_ * 2) + s * (NP_ * 2);
    float a0 = awp[0], a1 = awp[1], a2 = awp[2], a3 = awp[3];
    float mx = fmaxf(fmaxf(a0, a1), fmaxf(a2, a3));
    float e0 = expf(a0 - mx), e1 = expf(a1 - mx), e2 = expf(a2 - mx), e3 = expf(a3 - mx);
    float inv = 1.0f / (e0 + e1 + e2 + e3);
    float w[4] = {e0 * inv, e1 * inv, e2 * inv, e3 * inv};

    // off/norm in normalized coords -> *W in pixel coords: off * (W/200) = off (W==200)
    float4* out = g_scw + (((size_t)r * NS_ + s) * NH_ + h) * NP_;
    #pragma unroll
    for (int p = 0; p < 4; p++)
        out[p] = make_float4(xb + offp[2 * p], yb + offp[2 * p + 1], w[p], 0.0f);
}

// ---------------- deformable sampling ----------------
// One block per (r, s); warp = one head, lane = one channel -> each tap is a
// 128B coalesced line from g_vimg.
__global__ __launch_bounds__(256) void sample_kernel()
{
    const int blk = blockIdx.x;          // r*NS + s
    const int r = blk / NS_;
    const int s = blk - r * NS_;
    const int b = r / NQ_;
    __shared__ float4 sh[NH_ * NP_];
    const int t = threadIdx.x;
    if (t < NH_ * NP_) sh[t] = g_scw[(size_t)blk * (NH_ * NP_) + t];
    __syncthreads();

    const int h = t >> 5, dh = t & 31;
    const float* img = g_vimg + (size_t)(b * NH_ + h) * V_ * DH_;
    float acc = 0.0f;
    #pragma unroll
    for (int p = 0; p < NP_; p++) {
        float4 s4 = sh[h * NP_ + p];
        float x = s4.x, y = s4.y, w = s4.z;
        float xf = floorf(x), yf = floorf(y);
        int x0 = (int)xf, y0 = (int)yf;
        float wx1 = x - xf, wy1 = y - yf;
        float wx0 = 1.0f - wx1, wy0 = 1.0f - wy1;
        bool xv0 = (x0 >= 0) & (x0 < WB_);
        bool xv1 = (x0 + 1 >= 0) & (x0 + 1 < WB_);
        bool yv0 = (y0 >= 0) & (y0 < HB_);
        bool yv1 = (y0 + 1 >= 0) & (y0 + 1 < HB_);
        float v00 = 0.f, v10 = 0.f, v01 = 0.f, v11 = 0.f;
        if (xv0 && yv0) v00 = img[((size_t)(y0 * WB_ + x0)) * DH_ + dh];
        if (xv1 && yv0) v10 = img[((size_t)(y0 * WB_ + x0 + 1)) * DH_ + dh];
        if (xv0 && yv1) v01 = img[((size_t)((y0 + 1) * WB_ + x0)) * DH_ + dh];
        if (xv1 && yv1) v11 = img[((size_t)((y0 + 1) * WB_ + x0 + 1)) * DH_ + dh];
        acc += w * (v00 * wx0 * wy0 + v10 * wx1 * wy0 + v01 * wx0 * wy1 + v11 * wx1 * wy1);
    }
    // column order matches reference reshape: (s, h, dh)
    g_samp[(size_t)r * (NS_ * D_) + s * D_ + h * DH_ + dh] = acc;
}

// ---------------- LayerNorm + ReLU + residual ----------------
__global__ __launch_bounds__(256) void ln_relu_res(
    const float* __restrict__ query, const float* __restrict__ gam,
    const float* __restrict__ bet, float* __restrict__ out)
{
    const int r = blockIdx.x;
    const int d = threadIdx.x;
    float v = g_o[(size_t)r * D_ + d];
    float s1 = v, s2 = v * v;
    __shared__ float shs[8], shq[8];
    const int lane = d & 31, w = d >> 5;
    #pragma unroll
    for (int o = 16; o; o >>= 1) {
        s1 += __shfl_xor_sync(0xffffffffu, s1, o);
        s2 += __shfl_xor_sync(0xffffffffu, s2, o);
    }
    if (lane == 0) { shs[w] = s1; shq[w] = s2; }
    __syncthreads();
    if (d == 0) {
        float t1 = 0.f, t2 = 0.f;
        #pragma unroll
        for (int i = 0; i < 8; i++) { t1 += shs[i]; t2 += shq[i]; }
        shs[0] = t1 * (1.0f / D_);
        shq[0] = t2 * (1.0f / D_);
    }
    __syncthreads();
    float mu = shs[0];
    float var = shq[0] - mu * mu;
    float y = (v - mu) * rsqrtf(var + LN_EPS) * gam[d] + bet[d];
    y = fmaxf(y, 0.0f);
    out[(size_t)r * D_ + d] = y + query[(size_t)r * D_ + d];
}

// ---------------- launch (kernel launches ONLY — graph-capture safe) ----------------
extern "C" void kernel_launch(void* const* d_in, const int* in_sizes, int n_in,
                              void* d_out, int out_size)
{
    const float* query      = (const float*)d_in[0];
    const float* query_pos  = (const float*)d_in[1];
    const float* value      = (const float*)d_in[2];
    const float* ref_trajs  = (const float*)d_in[3];
    const float* centers    = (const float*)d_in[4];
    const float* W_off      = (const float*)d_in[5];
    const float* b_off      = (const float*)d_in[6];
    const float* W_attn     = (const float*)d_in[7];
    const float* b_attn     = (const float*)d_in[8];
    const float* W_val      = (const float*)d_in[9];
    const float* b_val      = (const float*)d_in[10];
    const float* W_out      = (const float*)d_in[11];
    const float* b_out      = (const float*)d_in[12];
    const float* ln_g       = (const float*)d_in[13];
    const float* ln_b       = (const float*)d_in[14];
    float* out = (float*)d_out;

    // 1) value projection + layout transform: (80000x256)@(256x256) -> g_vimg
    gemm_val<<<dim3(4, (BS_ * V_) / 64), 256>>>(value, W_val, b_val);

    // 2) offset + attention projections: (3072x256)@(256x768 / 256x384)
    gemm_qproj<<<dim3(768 / 64, ROWS_ / 64), 256>>>(query, query_pos, W_off, b_off, 768, 0);
    gemm_qproj<<<dim3(384 / 64, ROWS_ / 64), 256>>>(query, query_pos, W_attn, b_attn, 384, 1);

    // 3) softmax + sampling coordinates
    coords_softmax<<<(ROWS_ * NH_ * NS_ + 255) / 256, 256>>>(ref_trajs, centers);

    // 4) bilinear gather + attention-weighted sum
    sample_kernel<<<ROWS_ * NS_, 256>>>();

    // 5) output projection: (3072x3072)@(3072x256)
    gemm_out<<<dim3(D_ / 64, ROWS_ / 64), 256>>>(W_out, b_out);

    // 6) LayerNorm + ReLU + residual
    ln_relu_res<<<ROWS_, 256>>>(query, ln_g, ln_b, out);
}

// round 11
// speedup vs baseline: 1.0592x; 1.0592x over previous
#include <cuda_runtime.h>
#include <cuda_bf16.h>

// ---------------- problem constants ----------------
#define D_     256
#define NH_    8
#define DH_    32
#define NS_    12
#define NP_    4
#define HB_    200
#define WB_    200
#define V_     (HB_*WB_)       // 40000
#define BS_    2
#define A_     256
#define M_     6
#define NQ_    (A_*M_)         // 1536
#define ROWS_  (BS_*NQ_)       // 3072
#define LN_EPS 1e-5f

#define BK_    32
#define ASTR_  68              // padded m-stride: 2-way (vs 4-way) store conflicts

// ---------------- device scratch (static, allocation-free) ----------------
__device__ __align__(16) float g_vimg[(size_t)BS_*NH_*V_*DH_];     // [b][h][pix][dh]
__device__ __align__(16) float g_off [(size_t)ROWS_*768];          // offsets GEMM out
__device__ __align__(16) float g_aw  [(size_t)ROWS_*384];          // attn logits GEMM out
__device__ __align__(16) float4 g_scw[(size_t)ROWS_*NS_*NH_*NP_];  // (x, y, weight, pad)
__device__ __align__(16) float g_samp[(size_t)ROWS_*NS_*D_];       // sampled (3072, 3072)
__device__ __align__(16) float g_o   [(size_t)ROWS_*D_];           // pre-LN projection out

// ---------------- generic SGEMM: C = (A [+Aadd]) @ B + bias ----------------
// A: M x K row-major, B: K x N row-major. M%64==0, N%64==0, K%32==0.
__global__ __launch_bounds__(256) void sgemm_bias(
    const float* __restrict__ A, const float* __restrict__ Aadd,
    const float* __restrict__ B, const float* __restrict__ bias,
    float* __restrict__ C, int M, int N, int K)
{
    __shared__ float As[BK_][ASTR_];
    __shared__ float Bs[BK_][64];
    const int tid = threadIdx.x;
    const int tx = tid & 15, ty = tid >> 4;
    const int row0 = blockIdx.y * 64;
    const int col0 = blockIdx.x * 64;
    // A tile 64x32: 2 float4/thread; rows tid>>3 and tid>>3+32, cols (tid&7)*4
    const int a_m = tid >> 3, a_k = (tid & 7) << 2;
    // B tile 32x64: 2 float4/thread; rows tid>>4 and tid>>4+16, cols (tid&15)*4
    const int b_k = tid >> 4, b_n = (tid & 15) << 2;

    float acc[4][4] = {};
    for (int k0 = 0; k0 < K; k0 += BK_) {
        float4 av0 = *reinterpret_cast<const float4*>(&A[(size_t)(row0 + a_m) * K + k0 + a_k]);
        float4 av1 = *reinterpret_cast<const float4*>(&A[(size_t)(row0 + a_m + 32) * K + k0 + a_k]);
        if (Aadd) {
            float4 p0 = *reinterpret_cast<const float4*>(&Aadd[(size_t)(row0 + a_m) * K + k0 + a_k]);
            av0.x += p0.x; av0.y += p0.y; av0.z += p0.z; av0.w += p0.w;
            float4 p1 = *reinterpret_cast<const float4*>(&Aadd[(size_t)(row0 + a_m + 32) * K + k0 + a_k]);
            av1.x += p1.x; av1.y += p1.y; av1.z += p1.z; av1.w += p1.w;
        }
        As[a_k + 0][a_m] = av0.x;
        As[a_k + 1][a_m] = av0.y;
        As[a_k + 2][a_m] = av0.z;
        As[a_k + 3][a_m] = av0.w;
        As[a_k + 0][a_m + 32] = av1.x;
        As[a_k + 1][a_m + 32] = av1.y;
        As[a_k + 2][a_m + 32] = av1.z;
        As[a_k + 3][a_m + 32] = av1.w;
        *reinterpret_cast<float4*>(&Bs[b_k][b_n]) =
            *reinterpret_cast<const float4*>(&B[(size_t)(k0 + b_k) * N + col0 + b_n]);
        *reinterpret_cast<float4*>(&Bs[b_k + 16][b_n]) =
            *reinterpret_cast<const float4*>(&B[(size_t)(k0 + b_k + 16) * N + col0 + b_n]);
        __syncthreads();
        #pragma unroll
        for (int k = 0; k < BK_; k++) {
            float am[4], bn[4];
            #pragma unroll
            for (int i = 0; i < 4; i++) am[i] = As[k][ty * 4 + i];
            #pragma unroll
            for (int j = 0; j < 4; j++) bn[j] = Bs[k][tx * 4 + j];
            #pragma unroll
            for (int i = 0; i < 4; i++)
                #pragma unroll
                for (int j = 0; j < 4; j++) acc[i][j] += am[i] * bn[j];
        }
        __syncthreads();
    }
    const int col = col0 + tx * 4;
    float4 bv = *reinterpret_cast<const float4*>(&bias[col]);
    #pragma unroll
    for (int i = 0; i < 4; i++) {
        int row = row0 + ty * 4 + i;
        float4 o = make_float4(acc[i][0] + bv.x, acc[i][1] + bv.y,
                               acc[i][2] + bv.z, acc[i][3] + bv.w);
        *reinterpret_cast<float4*>(&C[(size_t)row * N + col]) = o;
    }
}

// ---------------- value projection GEMM with fused layout scatter ----------------
// Input: value (V, BS, D). Row r (= b*V + pix) of the logical A is value[pix][b][:].
// Output written directly to v_img[b][h][pix][dh] so the sampler gathers 128B lines.
// M = 80000 (blocks never straddle the b boundary: 40000 % 64 == 0).
__global__ __launch_bounds__(256) void gemm_val(
    const float* __restrict__ value, const float* __restrict__ W,
    const float* __restrict__ bias, float* __restrict__ vimg)
{
    __shared__ float As[BK_][ASTR_];
    __shared__ float Bs[BK_][64];
    const int tid = threadIdx.x;
    const int tx = tid & 15, ty = tid >> 4;
    const int row0 = blockIdx.y * 64;
    const int col0 = blockIdx.x * 64;
    const int bb = (row0 >= V_) ? 1 : 0;
    const int pix0 = row0 - bb * V_;
    const int a_m = tid >> 3, a_k = (tid & 7) << 2;
    const int b_k = tid >> 4, b_n = (tid & 15) << 2;
    const float* Arow0 = value + ((size_t)(pix0 + a_m) * BS_ + bb) * D_;
    const float* Arow1 = value + ((size_t)(pix0 + a_m + 32) * BS_ + bb) * D_;

    float acc[4][4] = {};
    for (int k0 = 0; k0 < 256; k0 += BK_) {
        float4 av0 = *reinterpret_cast<const float4*>(Arow0 + k0 + a_k);
        float4 av1 = *reinterpret_cast<const float4*>(Arow1 + k0 + a_k);
        As[a_k + 0][a_m] = av0.x;
        As[a_k + 1][a_m] = av0.y;
        As[a_k + 2][a_m] = av0.z;
        As[a_k + 3][a_m] = av0.w;
        As[a_k + 0][a_m + 32] = av1.x;
        As[a_k + 1][a_m + 32] = av1.y;
        As[a_k + 2][a_m + 32] = av1.z;
        As[a_k + 3][a_m + 32] = av1.w;
        *reinterpret_cast<float4*>(&Bs[b_k][b_n]) =
            *reinterpret_cast<const float4*>(&W[(size_t)(k0 + b_k) * 256 + col0 + b_n]);
        *reinterpret_cast<float4*>(&Bs[b_k + 16][b_n]) =
            *reinterpret_cast<const float4*>(&W[(size_t)(k0 + b_k + 16) * 256 + col0 + b_n]);
        __syncthreads();
        #pragma unroll
        for (int k = 0; k < BK_; k++) {
            float am[4], bn[4];
            #pragma unroll
            for (int i = 0; i < 4; i++) am[i] = As[k][ty * 4 + i];
            #pragma unroll
            for (int j = 0; j < 4; j++) bn[j] = Bs[k][tx * 4 + j];
            #pragma unroll
            for (int i = 0; i < 4; i++)
                #pragma unroll
                for (int j = 0; j < 4; j++) acc[i][j] += am[i] * bn[j];
        }
        __syncthreads();
    }
    const int col = col0 + tx * 4;           // 4 consecutive channels, same head
    const int h = col >> 5, dh = col & 31;
    float4 bv = *reinterpret_cast<const float4*>(&bias[col]);
    #pragma unroll
    for (int i = 0; i < 4; i++) {
        int pix = pix0 + ty * 4 + i;
        float4 o = make_float4(acc[i][0] + bv.x, acc[i][1] + bv.y,
                               acc[i][2] + bv.z, acc[i][3] + bv.w);
        *reinterpret_cast<float4*>(
            &vimg[(((size_t)(bb * NH_ + h)) * V_ + pix) * DH_ + dh]) = o;
    }
}

// ---------------- softmax + sampling-coordinate precompute ----------------
__global__ __launch_bounds__(256) void coords_softmax(
    const float* __restrict__ trajs, const float* __restrict__ centers,
    float4* __restrict__ scw)
{
    int gid = blockIdx.x * blockDim.x + threadIdx.x;
    if (gid >= ROWS_ * NH_ * NS_) return;
    int r = gid / (NH_ * NS_);
    int rem = gid - r * (NH_ * NS_);
    int h = rem / NS_;
    int s = rem - h * NS_;
    int b = r / NQ_;
    int q = r - b * NQ_;
    int a = q / M_;
    // reference point: trajs[b][a][m][NS-1][0][:] + det_centers[b][a][:]
    const float* tr = trajs + ((size_t)(((b * A_ + a) * M_ + (q - a * M_)) * NS_ + (NS_ - 1))) * 2;
    float cx = centers[(b * A_ + a) * 2 + 0];
    float cy = centers[(b * A_ + a) * 2 + 1];
    const float sc = 200.0f / 102.4f;
    float xb = (tr[0] + cx + 51.2f) * sc - 0.5f;
    float yb = (tr[1] + cy + 51.2f) * sc - 0.5f;

    const float* awp  = g_aw  + (size_t)r * 384 + h * (NS_ * NP_) + s * NP_;
    const float* offp = g_off + (size_t)r * 768 + h * (NS_ * NP_ * 2) + s * (NP_ * 2);
    float a0 = awp[0], a1 = awp[1], a2 = awp[2], a3 = awp[3];
    float mx = fmaxf(fmaxf(a0, a1), fmaxf(a2, a3));
    float e0 = expf(a0 - mx), e1 = expf(a1 - mx), e2 = expf(a2 - mx), e3 = expf(a3 - mx);
    float inv = 1.0f / (e0 + e1 + e2 + e3);
    float w[4] = {e0 * inv, e1 * inv, e2 * inv, e3 * inv};

    float4* out = scw + (((size_t)r * NS_ + s) * NH_ + h) * NP_;
    #pragma unroll
    for (int p = 0; p < 4; p++)
        out[p] = make_float4(xb + offp[2 * p], yb + offp[2 * p + 1], w[p], 0.0f);
}

// ---------------- deformable sampling ----------------
// One block per (b, q, s); warp = one head, lane = one channel -> each tap is
// a 128B coalesced line from v_img.
__global__ __launch_bounds__(256) void sample_kernel(
    const float* __restrict__ vimg, const float4* __restrict__ scw,
    float* __restrict__ outp)
{
    const int blk = blockIdx.x;          // r*NS + s
    const int r = blk / NS_;
    const int s = blk - r * NS_;
    const int b = r / NQ_;
    __shared__ float4 sh[NH_ * NP_];
    const int t = threadIdx.x;
    if (t < NH_ * NP_) sh[t] = scw[(size_t)blk * (NH_ * NP_) + t];
    __syncthreads();

    const int h = t >> 5, dh = t & 31;
    const float* img = vimg + (size_t)(b * NH_ + h) * V_ * DH_;
    float acc = 0.0f;
    #pragma unroll
    for (int p = 0; p < NP_; p++) {
        float4 s4 = sh[h * NP_ + p];
        float x = s4.x, y = s4.y, w = s4.z;
        float xf = floorf(x), yf = floorf(y);
        int x0 = (int)xf, y0 = (int)yf;
        float wx1 = x - xf, wy1 = y - yf;
        float wx0 = 1.0f - wx1, wy0 = 1.0f - wy1;
        bool xv0 = (x0 >= 0) & (x0 < WB_);
        bool xv1 = (x0 + 1 >= 0) & (x0 + 1 < WB_);
        bool yv0 = (y0 >= 0) & (y0 < HB_);
        bool yv1 = (y0 + 1 >= 0) & (y0 + 1 < HB_);
        float v00 = 0.f, v10 = 0.f, v01 = 0.f, v11 = 0.f;
        if (xv0 && yv0) v00 = img[((size_t)(y0 * WB_ + x0)) * DH_ + dh];
        if (xv1 && yv0) v10 = img[((size_t)(y0 * WB_ + x0 + 1)) * DH_ + dh];
        if (xv0 && yv1) v01 = img[((size_t)((y0 + 1) * WB_ + x0)) * DH_ + dh];
        if (xv1 && yv1) v11 = img[((size_t)((y0 + 1) * WB_ + x0 + 1)) * DH_ + dh];
        acc += w * (v00 * wx0 * wy0 + v10 * wx1 * wy0 + v01 * wx0 * wy1 + v11 * wx1 * wy1);
    }
    outp[(size_t)r * (NS_ * D_) + s * D_ + h * DH_ + dh] = acc;
}

// ---------------- LayerNorm + ReLU + residual ----------------
__global__ __launch_bounds__(256) void ln_relu_res(
    const float* __restrict__ O, const float* __restrict__ query,
    const float* __restrict__ gam, const float* __restrict__ bet,
    float* __restrict__ out)
{
    const int r = blockIdx.x;
    const int d = threadIdx.x;
    float v = O[(size_t)r * D_ + d];
    float s1 = v, s2 = v * v;
    __shared__ float shs[8], shq[8];
    const int lane = d & 31, w = d >> 5;
    #pragma unroll
    for (int o = 16; o; o >>= 1) {
        s1 += __shfl_xor_sync(0xffffffffu, s1, o);
        s2 += __shfl_xor_sync(0xffffffffu, s2, o);
    }
    if (lane == 0) { shs[w] = s1; shq[w] = s2; }
    __syncthreads();
    if (d == 0) {
        float t1 = 0.f, t2 = 0.f;
        #pragma unroll
        for (int i = 0; i < 8; i++) { t1 += shs[i]; t2 += shq[i]; }
        shs[0] = t1 * (1.0f / D_);
        shq[0] = t2 * (1.0f / D_);
    }
    __syncthreads();
    float mu = shs[0];
    float var = shq[0] - mu * mu;
    float y = (v - mu) * rsqrtf(var + LN_EPS) * gam[d] + bet[d];
    y = fmaxf(y, 0.0f);
    out[(size_t)r * D_ + d] = y + query[(size_t)r * D_ + d];
}

// ---------------- launch ----------------
extern "C" void kernel_launch(void* const* d_in, const int* in_sizes, int n_in,
                              void* d_out, int out_size)
{
    const float* query      = (const float*)d_in[0];
    const float* query_pos  = (const float*)d_in[1];
    const float* value      = (const float*)d_in[2];
    const float* ref_trajs  = (const float*)d_in[3];
    const float* centers    = (const float*)d_in[4];
    const float* W_off      = (const float*)d_in[5];
    const float* b_off      = (const float*)d_in[6];
    const float* W_attn     = (const float*)d_in[7];
    const float* b_attn     = (const float*)d_in[8];
    const float* W_val      = (const float*)d_in[9];
    const float* b_val      = (const float*)d_in[10];
    const float* W_out      = (const float*)d_in[11];
    const float* b_out      = (const float*)d_in[12];
    const float* ln_g       = (const float*)d_in[13];
    const float* ln_b       = (const float*)d_in[14];
    float* out = (float*)d_out;

    float *vimg, *offb, *awb, *samp, *ob;
    float4* scw;
    cudaGetSymbolAddress((void**)&vimg, g_vimg);
    cudaGetSymbolAddress((void**)&offb, g_off);
    cudaGetSymbolAddress((void**)&awb,  g_aw);
    cudaGetSymbolAddress((void**)&scw,  g_scw);
    cudaGetSymbolAddress((void**)&samp, g_samp);
    cudaGetSymbolAddress((void**)&ob,   g_o);

    // 1) value projection + layout transform: (80000x256)@(256x256) -> v_img
    gemm_val<<<dim3(4, (BS_ * V_) / 64), 256>>>(value, W_val, b_val, vimg);

    // 2) offset + attention projections: (3072x256)@(256x768 / 256x384)
    sgemm_bias<<<dim3(768 / 64, ROWS_ / 64), 256>>>(query, query_pos, W_off, b_off, offb, ROWS_, 768, 256);
    sgemm_bias<<<dim3(384 / 64, ROWS_ / 64), 256>>>(query, query_pos, W_attn, b_attn, awb, ROWS_, 384, 256);

    // 3) softmax + sampling coordinates
    coords_softmax<<<(ROWS_ * NH_ * NS_ + 255) / 256, 256>>>(ref_trajs, centers, scw);

    // 4) bilinear gather + attention-weighted sum
    sample_kernel<<<ROWS_ * NS_, 256>>>(vimg, scw, samp);

    // 5) output projection: (3072x3072)@(3072x256)
    sgemm_bias<<<dim3(D_ / 64, ROWS_ / 64), 256>>>(samp, nullptr, W_out, b_out, ob, ROWS_, D_, 3072);

    // 6) LayerNorm + ReLU + residual
    ln_relu_res<<<ROWS_, 256>>>(ob, query, ln_g, ln_b, out);
}

// round 12
// speedup vs baseline: 1.1920x; 1.1254x over previous
#include <cuda_runtime.h>
#include <cuda_bf16.h>

// ---------------- problem constants ----------------
#define D_     256
#define NH_    8
#define DH_    32
#define NS_    12
#define NP_    4
#define HB_    200
#define WB_    200
#define V_     (HB_*WB_)       // 40000
#define BS_    2
#define A_     256
#define M_     6
#define NQ_    (A_*M_)         // 1536
#define ROWS_  (BS_*NQ_)       // 3072
#define LN_EPS 1e-5f

#define BK_    32
#define ASTR_  68              // padded m-stride: 2-way (vs 4-way) store conflicts
#define KSPLIT 4               // split-K factor for the out-projection GEMM

// ---------------- device scratch (static, allocation-free) ----------------
__device__ __align__(16) float g_vimg[(size_t)BS_*NH_*V_*DH_];     // [b][h][pix][dh]
__device__ __align__(16) float g_off [(size_t)ROWS_*768];          // offsets GEMM out
__device__ __align__(16) float g_aw  [(size_t)ROWS_*384];          // attn logits GEMM out
__device__ __align__(16) float4 g_scw[(size_t)ROWS_*NS_*NH_*NP_];  // (x, y, weight, pad)
__device__ __align__(16) float g_samp[(size_t)ROWS_*NS_*D_];       // sampled (3072, 3072)
__device__ __align__(16) float g_opart[(size_t)KSPLIT*ROWS_*D_];   // split-K partials

// ---------------- generic SGEMM: C = (A [+Aadd]) @ B + bias ----------------
// A: M x K row-major, B: K x N row-major. M%64==0, N%64==0, K%32==0.
__global__ __launch_bounds__(256) void sgemm_bias(
    const float* __restrict__ A, const float* __restrict__ Aadd,
    const float* __restrict__ B, const float* __restrict__ bias,
    float* __restrict__ C, int M, int N, int K)
{
    __shared__ float As[BK_][ASTR_];
    __shared__ float Bs[BK_][64];
    const int tid = threadIdx.x;
    const int tx = tid & 15, ty = tid >> 4;
    const int row0 = blockIdx.y * 64;
    const int col0 = blockIdx.x * 64;
    const int a_m = tid >> 3, a_k = (tid & 7) << 2;
    const int b_k = tid >> 4, b_n = (tid & 15) << 2;

    float acc[4][4] = {};
    for (int k0 = 0; k0 < K; k0 += BK_) {
        float4 av0 = *reinterpret_cast<const float4*>(&A[(size_t)(row0 + a_m) * K + k0 + a_k]);
        float4 av1 = *reinterpret_cast<const float4*>(&A[(size_t)(row0 + a_m + 32) * K + k0 + a_k]);
        if (Aadd) {
            float4 p0 = *reinterpret_cast<const float4*>(&Aadd[(size_t)(row0 + a_m) * K + k0 + a_k]);
            av0.x += p0.x; av0.y += p0.y; av0.z += p0.z; av0.w += p0.w;
            float4 p1 = *reinterpret_cast<const float4*>(&Aadd[(size_t)(row0 + a_m + 32) * K + k0 + a_k]);
            av1.x += p1.x; av1.y += p1.y; av1.z += p1.z; av1.w += p1.w;
        }
        As[a_k + 0][a_m] = av0.x;
        As[a_k + 1][a_m] = av0.y;
        As[a_k + 2][a_m] = av0.z;
        As[a_k + 3][a_m] = av0.w;
        As[a_k + 0][a_m + 32] = av1.x;
        As[a_k + 1][a_m + 32] = av1.y;
        As[a_k + 2][a_m + 32] = av1.z;
        As[a_k + 3][a_m + 32] = av1.w;
        *reinterpret_cast<float4*>(&Bs[b_k][b_n]) =
            *reinterpret_cast<const float4*>(&B[(size_t)(k0 + b_k) * N + col0 + b_n]);
        *reinterpret_cast<float4*>(&Bs[b_k + 16][b_n]) =
            *reinterpret_cast<const float4*>(&B[(size_t)(k0 + b_k + 16) * N + col0 + b_n]);
        __syncthreads();
        #pragma unroll
        for (int k = 0; k < BK_; k++) {
            float am[4], bn[4];
            #pragma unroll
            for (int i = 0; i < 4; i++) am[i] = As[k][ty * 4 + i];
            #pragma unroll
            for (int j = 0; j < 4; j++) bn[j] = Bs[k][tx * 4 + j];
            #pragma unroll
            for (int i = 0; i < 4; i++)
                #pragma unroll
                for (int j = 0; j < 4; j++) acc[i][j] += am[i] * bn[j];
        }
        __syncthreads();
    }
    const int col = col0 + tx * 4;
    float4 bv = *reinterpret_cast<const float4*>(&bias[col]);
    #pragma unroll
    for (int i = 0; i < 4; i++) {
        int row = row0 + ty * 4 + i;
        float4 o = make_float4(acc[i][0] + bv.x, acc[i][1] + bv.y,
                               acc[i][2] + bv.z, acc[i][3] + bv.w);
        *reinterpret_cast<float4*>(&C[(size_t)row * N + col]) = o;
    }
}

// ---------------- split-K out-projection: partial[z] = A[:,z*768:+768] @ B[z*768:,:] ----
// A = g_samp (3072 x 3072), B = W_out (3072 x 256). blockIdx.z = K-slice.
// No bias here; reduction + bias folded into ln_relu_res.
__global__ __launch_bounds__(256) void gemm_out_splitk(
    const float* __restrict__ B)
{
    __shared__ float As[BK_][ASTR_];
    __shared__ float Bs[BK_][64];
    const int tid = threadIdx.x;
    const int tx = tid & 15, ty = tid >> 4;
    const int row0 = blockIdx.y * 64;
    const int col0 = blockIdx.x * 64;
    const int slice = blockIdx.z;
    const int kbase = slice * (3072 / KSPLIT);    // 768 per slice
    const int a_m = tid >> 3, a_k = (tid & 7) << 2;
    const int b_k = tid >> 4, b_n = (tid & 15) << 2;
    float* __restrict__ C = g_opart + (size_t)slice * ROWS_ * D_;

    float acc[4][4] = {};
    for (int kk = 0; kk < 3072 / KSPLIT; kk += BK_) {
        const int k0 = kbase + kk;
        float4 av0 = *reinterpret_cast<const float4*>(&g_samp[(size_t)(row0 + a_m) * 3072 + k0 + a_k]);
        float4 av1 = *reinterpret_cast<const float4*>(&g_samp[(size_t)(row0 + a_m + 32) * 3072 + k0 + a_k]);
        As[a_k + 0][a_m] = av0.x;
        As[a_k + 1][a_m] = av0.y;
        As[a_k + 2][a_m] = av0.z;
        As[a_k + 3][a_m] = av0.w;
        As[a_k + 0][a_m + 32] = av1.x;
        As[a_k + 1][a_m + 32] = av1.y;
        As[a_k + 2][a_m + 32] = av1.z;
        As[a_k + 3][a_m + 32] = av1.w;
        *reinterpret_cast<float4*>(&Bs[b_k][b_n]) =
            *reinterpret_cast<const float4*>(&B[(size_t)(k0 + b_k) * 256 + col0 + b_n]);
        *reinterpret_cast<float4*>(&Bs[b_k + 16][b_n]) =
            *reinterpret_cast<const float4*>(&B[(size_t)(k0 + b_k + 16) * 256 + col0 + b_n]);
        __syncthreads();
        #pragma unroll
        for (int k = 0; k < BK_; k++) {
            float am[4], bn[4];
            #pragma unroll
            for (int i = 0; i < 4; i++) am[i] = As[k][ty * 4 + i];
            #pragma unroll
            for (int j = 0; j < 4; j++) bn[j] = Bs[k][tx * 4 + j];
            #pragma unroll
            for (int i = 0; i < 4; i++)
                #pragma unroll
                for (int j = 0; j < 4; j++) acc[i][j] += am[i] * bn[j];
        }
        __syncthreads();
    }
    const int col = col0 + tx * 4;
    #pragma unroll
    for (int i = 0; i < 4; i++) {
        int row = row0 + ty * 4 + i;
        *reinterpret_cast<float4*>(&C[(size_t)row * 256 + col]) =
            make_float4(acc[i][0], acc[i][1], acc[i][2], acc[i][3]);
    }
}

// ---------------- value projection GEMM with fused layout scatter ----------------
__global__ __launch_bounds__(256) void gemm_val(
    const float* __restrict__ value, const float* __restrict__ W,
    const float* __restrict__ bias, float* __restrict__ vimg)
{
    __shared__ float As[BK_][ASTR_];
    __shared__ float Bs[BK_][64];
    const int tid = threadIdx.x;
    const int tx = tid & 15, ty = tid >> 4;
    const int row0 = blockIdx.y * 64;
    const int col0 = blockIdx.x * 64;
    const int bb = (row0 >= V_) ? 1 : 0;
    const int pix0 = row0 - bb * V_;
    const int a_m = tid >> 3, a_k = (tid & 7) << 2;
    const int b_k = tid >> 4, b_n = (tid & 15) << 2;
    const float* Arow0 = value + ((size_t)(pix0 + a_m) * BS_ + bb) * D_;
    const float* Arow1 = value + ((size_t)(pix0 + a_m + 32) * BS_ + bb) * D_;

    float acc[4][4] = {};
    for (int k0 = 0; k0 < 256; k0 += BK_) {
        float4 av0 = *reinterpret_cast<const float4*>(Arow0 + k0 + a_k);
        float4 av1 = *reinterpret_cast<const float4*>(Arow1 + k0 + a_k);
        As[a_k + 0][a_m] = av0.x;
        As[a_k + 1][a_m] = av0.y;
        As[a_k + 2][a_m] = av0.z;
        As[a_k + 3][a_m] = av0.w;
        As[a_k + 0][a_m + 32] = av1.x;
        As[a_k + 1][a_m + 32] = av1.y;
        As[a_k + 2][a_m + 32] = av1.z;
        As[a_k + 3][a_m + 32] = av1.w;
        *reinterpret_cast<float4*>(&Bs[b_k][b_n]) =
            *reinterpret_cast<const float4*>(&W[(size_t)(k0 + b_k) * 256 + col0 + b_n]);
        *reinterpret_cast<float4*>(&Bs[b_k + 16][b_n]) =
            *reinterpret_cast<const float4*>(&W[(size_t)(k0 + b_k + 16) * 256 + col0 + b_n]);
        __syncthreads();
        #pragma unroll
        for (int k = 0; k < BK_; k++) {
            float am[4], bn[4];
            #pragma unroll
            for (int i = 0; i < 4; i++) am[i] = As[k][ty * 4 + i];
            #pragma unroll
            for (int j = 0; j < 4; j++) bn[j] = Bs[k][tx * 4 + j];
            #pragma unroll
            for (int i = 0; i < 4; i++)
                #pragma unroll
                for (int j = 0; j < 4; j++) acc[i][j] += am[i] * bn[j];
        }
        __syncthreads();
    }
    const int col = col0 + tx * 4;           // 4 consecutive channels, same head
    const int h = col >> 5, dh = col & 31;
    float4 bv = *reinterpret_cast<const float4*>(&bias[col]);
    #pragma unroll
    for (int i = 0; i < 4; i++) {
        int pix = pix0 + ty * 4 + i;
        float4 o = make_float4(acc[i][0] + bv.x, acc[i][1] + bv.y,
                               acc[i][2] + bv.z, acc[i][3] + bv.w);
        *reinterpret_cast<float4*>(
            &vimg[(((size_t)(bb * NH_ + h)) * V_ + pix) * DH_ + dh]) = o;
    }
}

// ---------------- softmax + sampling-coordinate precompute ----------------
__global__ __launch_bounds__(256) void coords_softmax(
    const float* __restrict__ trajs, const float* __restrict__ centers,
    float4* __restrict__ scw)
{
    int gid = blockIdx.x * blockDim.x + threadIdx.x;
    if (gid >= ROWS_ * NH_ * NS_) return;
    int r = gid / (NH_ * NS_);
    int rem = gid - r * (NH_ * NS_);
    int h = rem / NS_;
    int s = rem - h * NS_;
    int b = r / NQ_;
    int q = r - b * NQ_;
    int a = q / M_;
    const float* tr = trajs + ((size_t)(((b * A_ + a) * M_ + (q - a * M_)) * NS_ + (NS_ - 1))) * 2;
    float cx = centers[(b * A_ + a) * 2 + 0];
    float cy = centers[(b * A_ + a) * 2 + 1];
    const float sc = 200.0f / 102.4f;
    float xb = (tr[0] + cx + 51.2f) * sc - 0.5f;
    float yb = (tr[1] + cy + 51.2f) * sc - 0.5f;

    const float* awp  = g_aw  + (size_t)r * 384 + h * (NS_ * NP_) + s * NP_;
    const float* offp = g_off + (size_t)r * 768 + h * (NS_ * NP_ * 2) + s * (NP_ * 2);
    float a0 = awp[0], a1 = awp[1], a2 = awp[2], a3 = awp[3];
    float mx = fmaxf(fmaxf(a0, a1), fmaxf(a2, a3));
    float e0 = expf(a0 - mx), e1 = expf(a1 - mx), e2 = expf(a2 - mx), e3 = expf(a3 - mx);
    float inv = 1.0f / (e0 + e1 + e2 + e3);
    float w[4] = {e0 * inv, e1 * inv, e2 * inv, e3 * inv};

    float4* out = scw + (((size_t)r * NS_ + s) * NH_ + h) * NP_;
    #pragma unroll
    for (int p = 0; p < 4; p++)
        out[p] = make_float4(xb + offp[2 * p], yb + offp[2 * p + 1], w[p], 0.0f);
}

// ---------------- deformable sampling ----------------
__global__ __launch_bounds__(256) void sample_kernel(
    const float* __restrict__ vimg, const float4* __restrict__ scw,
    float* __restrict__ outp)
{
    const int blk = blockIdx.x;          // r*NS + s
    const int r = blk / NS_;
    const int s = blk - r * NS_;
    const int b = r / NQ_;
    __shared__ float4 sh[NH_ * NP_];
    const int t = threadIdx.x;
    if (t < NH_ * NP_) sh[t] = scw[(size_t)blk * (NH_ * NP_) + t];
    __syncthreads();

    const int h = t >> 5, dh = t & 31;
    const float* img = vimg + (size_t)(b * NH_ + h) * V_ * DH_;
    float acc = 0.0f;
    #pragma unroll
    for (int p = 0; p < NP_; p++) {
        float4 s4 = sh[h * NP_ + p];
        float x = s4.x, y = s4.y, w = s4.z;
        float xf = floorf(x), yf = floorf(y);
        int x0 = (int)xf, y0 = (int)yf;
        float wx1 = x - xf, wy1 = y - yf;
        float wx0 = 1.0f - wx1, wy0 = 1.0f - wy1;
        bool xv0 = (x0 >= 0) & (x0 < WB_);
        bool xv1 = (x0 + 1 >= 0) & (x0 + 1 < WB_);
        bool yv0 = (y0 >= 0) & (y0 < HB_);
        bool yv1 = (y0 + 1 >= 0) & (y0 + 1 < HB_);
        float v00 = 0.f, v10 = 0.f, v01 = 0.f, v11 = 0.f;
        if (xv0 && yv0) v00 = img[((size_t)(y0 * WB_ + x0)) * DH_ + dh];
        if (xv1 && yv0) v10 = img[((size_t)(y0 * WB_ + x0 + 1)) * DH_ + dh];
        if (xv0 && yv1) v01 = img[((size_t)((y0 + 1) * WB_ + x0)) * DH_ + dh];
        if (xv1 && yv1) v11 = img[((size_t)((y0 + 1) * WB_ + x0 + 1)) * DH_ + dh];
        acc += w * (v00 * wx0 * wy0 + v10 * wx1 * wy0 + v01 * wx0 * wy1 + v11 * wx1 * wy1);
    }
    outp[(size_t)r * (NS_ * D_) + s * D_ + h * DH_ + dh] = acc;
}

// ---------------- LayerNorm + ReLU + residual (+ split-K reduction + bias) --------
__global__ __launch_bounds__(256) void ln_relu_res(
    const float* __restrict__ query, const float* __restrict__ bias,
    const float* __restrict__ gam, const float* __restrict__ bet,
    float* __restrict__ out)
{
    const int r = blockIdx.x;
    const int d = threadIdx.x;
    const size_t idx = (size_t)r * D_ + d;
    float v = g_opart[idx]
            + g_opart[(size_t)1 * ROWS_ * D_ + idx]
            + g_opart[(size_t)2 * ROWS_ * D_ + idx]
            + g_opart[(size_t)3 * ROWS_ * D_ + idx]
            + bias[d];
    float s1 = v, s2 = v * v;
    __shared__ float shs[8], shq[8];
    const int lane = d & 31, w = d >> 5;
    #pragma unroll
    for (int o = 16; o; o >>= 1) {
        s1 += __shfl_xor_sync(0xffffffffu, s1, o);
        s2 += __shfl_xor_sync(0xffffffffu, s2, o);
    }
    if (lane == 0) { shs[w] = s1; shq[w] = s2; }
    __syncthreads();
    if (d == 0) {
        float t1 = 0.f, t2 = 0.f;
        #pragma unroll
        for (int i = 0; i < 8; i++) { t1 += shs[i]; t2 += shq[i]; }
        shs[0] = t1 * (1.0f / D_);
        shq[0] = t2 * (1.0f / D_);
    }
    __syncthreads();
    float mu = shs[0];
    float var = shq[0] - mu * mu;
    float y = (v - mu) * rsqrtf(var + LN_EPS) * gam[d] + bet[d];
    y = fmaxf(y, 0.0f);
    out[idx] = y + query[idx];
}

// ---------------- launch ----------------
extern "C" void kernel_launch(void* const* d_in, const int* in_sizes, int n_in,
                              void* d_out, int out_size)
{
    const float* query      = (const float*)d_in[0];
    const float* query_pos  = (const float*)d_in[1];
    const float* value      = (const float*)d_in[2];
    const float* ref_trajs  = (const float*)d_in[3];
    const float* centers    = (const float*)d_in[4];
    const float* W_off      = (const float*)d_in[5];
    const float* b_off      = (const float*)d_in[6];
    const float* W_attn     = (const float*)d_in[7];
    const float* b_attn     = (const float*)d_in[8];
    const float* W_val      = (const float*)d_in[9];
    const float* b_val      = (const float*)d_in[10];
    const float* W_out      = (const float*)d_in[11];
    const float* b_out      = (const float*)d_in[12];
    const float* ln_g       = (const float*)d_in[13];
    const float* ln_b       = (const float*)d_in[14];
    float* out = (float*)d_out;

    float *vimg, *offb, *awb, *samp;
    float4* scw;
    cudaGetSymbolAddress((void**)&vimg, g_vimg);
    cudaGetSymbolAddress((void**)&offb, g_off);
    cudaGetSymbolAddress((void**)&awb,  g_aw);
    cudaGetSymbolAddress((void**)&scw,  g_scw);
    cudaGetSymbolAddress((void**)&samp, g_samp);

    // 1) value projection + layout transform: (80000x256)@(256x256) -> v_img
    gemm_val<<<dim3(4, (BS_ * V_) / 64), 256>>>(value, W_val, b_val, vimg);

    // 2) offset + attention projections: (3072x256)@(256x768 / 256x384)
    sgemm_bias<<<dim3(768 / 64, ROWS_ / 64), 256>>>(query, query_pos, W_off, b_off, offb, ROWS_, 768, 256);
    sgemm_bias<<<dim3(384 / 64, ROWS_ / 64), 256>>>(query, query_pos, W_attn, b_attn, awb, ROWS_, 384, 256);

    // 3) softmax + sampling coordinates
    coords_softmax<<<(ROWS_ * NH_ * NS_ + 255) / 256, 256>>>(ref_trajs, centers, scw);

    // 4) bilinear gather + attention-weighted sum
    sample_kernel<<<ROWS_ * NS_, 256>>>(vimg, scw, samp);

    // 5) output projection, split-K x4: (3072x3072)@(3072x256) -> 4 partials
    gemm_out_splitk<<<dim3(D_ / 64, ROWS_ / 64, KSPLIT), 256>>>(W_out);

    // 6) split-K reduce + bias + LayerNorm + ReLU + residual
    ln_relu_res<<<ROWS_, 256>>>(query, b_out, ln_g, ln_b, out);
}